// round 15
// baseline (speedup 1.0000x reference)
#include <cuda_runtime.h>
#include <cuda_fp16.h>
#include <math.h>
#include <stdint.h>

#define N_TOK   8192
#define D_MODEL 1024
#define H_DIM   512
#define N_EXP   8
#define TOPK    2
#define N_ASSIGN (N_TOK * TOPK)
#define TILE_M  128
#define MAX_TILES (N_ASSIGN / TILE_M + N_EXP)   // 136

// ------------------- device scratch -------------------
__device__ float g_h[(size_t)N_ASSIGN * H_DIM];
__device__ int   g_counts[N_EXP];
__device__ int   g_offsets[N_EXP + 1];
__device__ int   g_cursors[N_EXP];
__device__ int   g_rowToken[N_ASSIGN];
__device__ float g_tokw[N_TOK];
__device__ int   g_tokExperts[N_TOK * TOPK];
__device__ int   g_tileExpert[MAX_TILES];
__device__ int   g_tileRowStart[MAX_TILES];
__device__ int   g_tileRows[MAX_TILES];
__device__ int   g_numTiles;

// ------------------- helpers -------------------
__device__ __forceinline__ uint32_t pack2h(float lo, float hi) {
    __half2 h = __floats2half2_rn(lo, hi);   // .x = lo (low 16 bits), .y = hi
    return *(uint32_t*)&h;
}
__device__ __forceinline__ void mma_f16(float& c0, float& c1, float& c2, float& c3,
                                        uint32_t a0, uint32_t a1, uint32_t a2, uint32_t a3,
                                        uint32_t b0, uint32_t b1) {
    asm volatile("mma.sync.aligned.m16n8k16.row.col.f32.f16.f16.f32 "
                 "{%0,%1,%2,%3}, {%4,%5,%6,%7}, {%8,%9}, {%0,%1,%2,%3};"
                 : "+f"(c0), "+f"(c1), "+f"(c2), "+f"(c3)
                 : "r"(a0), "r"(a1), "r"(a2), "r"(a3), "r"(b0), "r"(b1));
}
__device__ __forceinline__ float gelu_exact(float v) {
    return 0.5f * v * (1.0f + erff(v * 0.70710678118654752f));
}

// ------------------- init: zero output + counters -------------------
__global__ void init_kernel(float* __restrict__ out) {
    int idx = blockIdx.x * blockDim.x + threadIdx.x;
    if (idx < (N_TOK * D_MODEL) / 4)
        ((float4*)out)[idx] = make_float4(0.f, 0.f, 0.f, 0.f);
    if (idx < N_EXP) g_counts[idx] = 0;
}

// ------------------- gating -------------------
__global__ void gate_kernel(const float* __restrict__ x, const float* __restrict__ gw) {
    int n = blockIdx.x;
    int tid = threadIdx.x;
    const float* xr = x + (size_t)n * D_MODEL;
    float acc[N_EXP];
#pragma unroll
    for (int e = 0; e < N_EXP; e++) acc[e] = 0.f;
    for (int d = tid; d < D_MODEL; d += 256) {
        float xv = xr[d];
        const float* g = gw + d * N_EXP;
#pragma unroll
        for (int e = 0; e < N_EXP; e++) acc[e] += xv * g[e];
    }
#pragma unroll
    for (int off = 16; off > 0; off >>= 1)
#pragma unroll
        for (int e = 0; e < N_EXP; e++)
            acc[e] += __shfl_down_sync(0xffffffffu, acc[e], off);
    __shared__ float s[8][N_EXP];
    int w = tid >> 5, l = tid & 31;
    if (l == 0)
#pragma unroll
        for (int e = 0; e < N_EXP; e++) s[w][e] = acc[e];
    __syncthreads();
    if (tid == 0) {
        float p[N_EXP];
#pragma unroll
        for (int e = 0; e < N_EXP; e++) {
            float v = 0.f;
#pragma unroll
            for (int ww = 0; ww < 8; ww++) v += s[ww][e];
            p[e] = v;
        }
        float mx = p[0];
#pragma unroll
        for (int e = 1; e < N_EXP; e++) mx = fmaxf(mx, p[e]);
        float sum = 0.f;
#pragma unroll
        for (int e = 0; e < N_EXP; e++) { p[e] = expf(p[e] - mx); sum += p[e]; }
        float inv = 1.f / sum;
#pragma unroll
        for (int e = 0; e < N_EXP; e++) p[e] *= inv;
        int i1 = 0;
#pragma unroll
        for (int e = 1; e < N_EXP; e++) if (p[e] > p[i1]) i1 = e;
        int i2 = (i1 == 0) ? 1 : 0;
#pragma unroll
        for (int e = 0; e < N_EXP; e++) if (e != i1 && p[e] > p[i2]) i2 = e;
        g_tokw[n] = p[i1] + p[i2];
        g_tokExperts[2 * n + 0] = i1;
        g_tokExperts[2 * n + 1] = i2;
        atomicAdd(&g_counts[i1], 1);
        atomicAdd(&g_counts[i2], 1);
    }
}

// ------------------- setup + scatter -------------------
__global__ void setup_kernel() {
    int off = 0;
    for (int e = 0; e < N_EXP; e++) { g_offsets[e] = off; g_cursors[e] = off; off += g_counts[e]; }
    g_offsets[N_EXP] = off;
    int t = 0;
    for (int e = 0; e < N_EXP; e++) {
        int c = g_counts[e];
        for (int r = 0; r < c; r += TILE_M) {
            g_tileExpert[t] = e; g_tileRowStart[t] = g_offsets[e] + r;
            g_tileRows[t] = min(TILE_M, c - r); t++;
        }
    }
    g_numTiles = t;
}
__global__ void scatter_kernel() {
    int n = blockIdx.x * blockDim.x + threadIdx.x;
    if (n >= N_TOK) return;
#pragma unroll
    for (int k = 0; k < TOPK; k++) {
        int e = g_tokExperts[2 * n + k];
        int pos = atomicAdd(&g_cursors[e], 1);
        g_rowToken[pos] = n;
    }
}

// ------------------- fp16 mma.sync grouped GEMM (R4 loop structure) -------------------
// Tile 128(M) x 128(N), BK=16 (one m16n8k16 K-step per tile).
// 8 warps: warp_m = wid&1 (x64), warp_n = wid>>1 (x32); 4x4 m16n8k16 per warp.
// SMEM words are k-pair-packed half2: word w of row r = halves {A[r][2w], A[r][2w+1]}.
// As[2][128][AW] words (AW=20): frag banks (20r + t4) = 4*(5q%8)+t4.. -> conflict-free.
// Bs[2][8][BW]  words (BW=136): word = k2*136 + n; frag banks 8*t4+quad -> conflict-free.
#define BK 16
#define AW 20
#define BW 136

struct Frag { float c[4][4][4]; };  // [mi][ni][reg]

template <int KDIM, bool FC1>
__device__ __forceinline__ void gemm_core(
    const float* __restrict__ aBase,   // FC1: x (gathered); FC2: g_h
    const float* __restrict__ bBase,   // weight [KDIM][N_total] row-major for this expert
    int nTotal, int n0, int rs, int nr, Frag& F)
{
    __shared__ __align__(16) uint32_t As[2][128][AW];
    __shared__ __align__(16) uint32_t Bs[2][BK / 2][BW];

    int tid = threadIdx.x;
    int lane = tid & 31, wid = tid >> 5;
    int quad = lane >> 2, t4 = lane & 3;
    int wm = (wid & 1) * 64, wn = (wid >> 1) * 32;

    // A: 2 threads/row, 8 floats each (2 float4); packed to 4 words -> 1 STS.128
    int arow = tid >> 1;
    int af0  = (tid & 1) * 8;          // float offset within BK
    int aw0  = (tid & 1) * 4;          // word offset in As row
    const float* aptr;
    bool avalid;
    if (FC1) {
        avalid = arow < nr;
        aptr = (avalid ? (aBase + (size_t)g_rowToken[rs + arow] * KDIM) : aBase) + af0;
    } else {
        avalid = true;
        int ar = rs + arow; if (ar >= N_ASSIGN) ar = N_ASSIGN - 1;
        aptr = aBase + (size_t)ar * KDIM + af0;
    }
    // B: warp-uniform k-pair row, lane-contiguous n (coalesced LDG.128):
    // k2 = tid>>5 (0..7), n = (tid&31)*4; loads rows 2*k2 and 2*k2+1.
    int bk2 = tid >> 5;
    int bn0 = (tid & 31) * 4;
    const float* bptr = bBase + (size_t)(2 * bk2) * nTotal + n0 + bn0;

#pragma unroll
    for (int mi = 0; mi < 4; mi++)
#pragma unroll
        for (int ni = 0; ni < 4; ni++)
#pragma unroll
            for (int rr = 0; rr < 4; rr++) F.c[mi][ni][rr] = 0.f;

    // ---- prologue: load tile 0, pack, store stage 0 ----
    {
        float4 a0 = avalid ? *(const float4*)(aptr + 0) : make_float4(0, 0, 0, 0);
        float4 a1 = avalid ? *(const float4*)(aptr + 4) : make_float4(0, 0, 0, 0);
        uint4 wa;
        wa.x = pack2h(a0.x, a0.y); wa.y = pack2h(a0.z, a0.w);
        wa.z = pack2h(a1.x, a1.y); wa.w = pack2h(a1.z, a1.w);
        *(uint4*)&As[0][arow][aw0] = wa;
        float4 blo = *(const float4*)(bptr);
        float4 bhi = *(const float4*)(bptr + nTotal);
        uint4 wb;
        wb.x = pack2h(blo.x, bhi.x); wb.y = pack2h(blo.y, bhi.y);
        wb.z = pack2h(blo.z, bhi.z); wb.w = pack2h(blo.w, bhi.w);
        *(uint4*)&Bs[0][bk2][bn0] = wb;
    }
    __syncthreads();

    const int NT = KDIM / BK;
    for (int t = 0; t < NT; t++) {
        int s = t & 1;
        float4 na0, na1, nblo, nbhi;
        bool more = (t + 1) < NT;
        if (more) {
            int k0 = (t + 1) * BK;
            na0 = avalid ? *(const float4*)(aptr + k0 + 0) : make_float4(0, 0, 0, 0);
            na1 = avalid ? *(const float4*)(aptr + k0 + 4) : make_float4(0, 0, 0, 0);
            const float* bS = bptr + (size_t)k0 * nTotal;
            nblo = *(const float4*)(bS);
            nbhi = *(const float4*)(bS + nTotal);
        }
        // ---- compute on stage s: one m16n8k16 K-step ----
        {
            uint32_t a[4][4], b[4][2];
#pragma unroll
            for (int mi = 0; mi < 4; mi++) {
                int r0 = wm + mi * 16 + quad;
                a[mi][0] = As[s][r0][t4];          // (row,   k 2t4..2t4+1)
                a[mi][1] = As[s][r0 + 8][t4];      // (row+8, k 2t4..)
                a[mi][2] = As[s][r0][t4 + 4];      // (row,   k 2t4+8..)
                a[mi][3] = As[s][r0 + 8][t4 + 4];  // (row+8, k 2t4+8..)
            }
#pragma unroll
            for (int ni = 0; ni < 4; ni++) {
                int cc = wn + ni * 8 + quad;
                b[ni][0] = Bs[s][t4][cc];          // k 2t4..2t4+1   at col
                b[ni][1] = Bs[s][t4 + 4][cc];      // k 2t4+8..+9    at col
            }
#pragma unroll
            for (int mi = 0; mi < 4; mi++)
#pragma unroll
                for (int ni = 0; ni < 4; ni++)
                    mma_f16(F.c[mi][ni][0], F.c[mi][ni][1], F.c[mi][ni][2], F.c[mi][ni][3],
                            a[mi][0], a[mi][1], a[mi][2], a[mi][3],
                            b[ni][0], b[ni][1]);
        }
        // ---- pack + store next tile into stage s^1 ----
        if (more) {
            int s1 = s ^ 1;
            uint4 wa;
            wa.x = pack2h(na0.x, na0.y); wa.y = pack2h(na0.z, na0.w);
            wa.z = pack2h(na1.x, na1.y); wa.w = pack2h(na1.z, na1.w);
            *(uint4*)&As[s1][arow][aw0] = wa;
            uint4 wb;
            wb.x = pack2h(nblo.x, nbhi.x); wb.y = pack2h(nblo.y, nbhi.y);
            wb.z = pack2h(nblo.z, nbhi.z); wb.w = pack2h(nblo.w, nbhi.w);
            *(uint4*)&Bs[s1][bk2][bn0] = wb;
        }
        __syncthreads();
    }
}

// fc1: h = gelu(x_gathered @ w1[e] + b1[e]); grid (MAX_TILES, H_DIM/128)
__global__ void __launch_bounds__(256, 2)
fc1_mma(const float* __restrict__ x, const float* __restrict__ w1,
        const float* __restrict__ b1) {
    int tile = blockIdx.x;
    if (tile >= g_numTiles) return;
    int e = g_tileExpert[tile], rs = g_tileRowStart[tile], nr = g_tileRows[tile];
    int n0 = blockIdx.y * 128;

    Frag F;
    gemm_core<D_MODEL, true>(x, w1 + (size_t)e * D_MODEL * H_DIM, H_DIM, n0, rs, nr, F);

    int tid = threadIdx.x, lane = tid & 31, wid = tid >> 5;
    int quad = lane >> 2, t4 = lane & 3;
    int wm = (wid & 1) * 64, wn = (wid >> 1) * 32;
    const float* b1e = b1 + e * H_DIM + n0;
#pragma unroll
    for (int mi = 0; mi < 4; mi++) {
#pragma unroll
        for (int half = 0; half < 2; half++) {
            int m = wm + mi * 16 + quad + half * 8;
            if (m < nr) {
                float* hrow = g_h + (size_t)(rs + m) * H_DIM + n0;
#pragma unroll
                for (int ni = 0; ni < 4; ni++) {
                    int cc = wn + ni * 8 + 2 * t4;
                    float v0 = F.c[mi][ni][half * 2 + 0] + b1e[cc];
                    float v1 = F.c[mi][ni][half * 2 + 1] + b1e[cc + 1];
                    *(float2*)(hrow + cc) = make_float2(gelu_exact(v0), gelu_exact(v1));
                }
            }
        }
    }
}

// fc2: out[token] += tokw * (h @ w2[e] + b2[e]); grid (MAX_TILES, D_MODEL/128)
__global__ void __launch_bounds__(256, 2)
fc2_mma(const float* __restrict__ w2, const float* __restrict__ b2,
        float* __restrict__ out) {
    int tile = blockIdx.x;
    if (tile >= g_numTiles) return;
    int e = g_tileExpert[tile], rs = g_tileRowStart[tile], nr = g_tileRows[tile];
    int n0 = blockIdx.y * 128;

    Frag F;
    gemm_core<H_DIM, false>(g_h, w2 + (size_t)e * H_DIM * D_MODEL, D_MODEL, n0, rs, nr, F);

    int tid = threadIdx.x, lane = tid & 31, wid = tid >> 5;
    int quad = lane >> 2, t4 = lane & 3;
    int wm = (wid & 1) * 64, wn = (wid >> 1) * 32;
    const float* b2e = b2 + e * D_MODEL + n0;
#pragma unroll
    for (int mi = 0; mi < 4; mi++) {
#pragma unroll
        for (int half = 0; half < 2; half++) {
            int m = wm + mi * 16 + quad + half * 8;
            if (m < nr) {
                int token = g_rowToken[rs + m];
                float wgt = g_tokw[token];
                float* orow = out + (size_t)token * D_MODEL + n0;
#pragma unroll
                for (int ni = 0; ni < 4; ni++) {
                    int cc = wn + ni * 8 + 2 * t4;
                    float v0 = F.c[mi][ni][half * 2 + 0] + b2e[cc];
                    float v1 = F.c[mi][ni][half * 2 + 1] + b2e[cc + 1];
                    atomicAdd(&orow[cc], wgt * v0);
                    atomicAdd(&orow[cc + 1], wgt * v1);
                }
            }
        }
    }
}

// ------------------- launch -------------------
extern "C" void kernel_launch(void* const* d_in, const int* in_sizes, int n_in,
                              void* d_out, int out_size) {
    const float* x      = (const float*)d_in[0];
    const float* gate_w = (const float*)d_in[1];
    const float* w1     = (const float*)d_in[2];
    const float* b1     = (const float*)d_in[3];
    const float* w2     = (const float*)d_in[4];
    const float* b2     = (const float*)d_in[5];
    float* out = (float*)d_out;

    init_kernel<<<(N_TOK * D_MODEL / 4 + 255) / 256, 256>>>(out);
    gate_kernel<<<N_TOK, 256>>>(x, gate_w);
    setup_kernel<<<1, 1>>>();
    scatter_kernel<<<(N_TOK + 255) / 256, 256>>>();
    {
        dim3 g(MAX_TILES, H_DIM / 128);
        fc1_mma<<<g, 256>>>(x, w1, b1);
    }
    {
        dim3 g(MAX_TILES, D_MODEL / 128);
        fc2_mma<<<g, 256>>>(w2, b2, out);
    }
}